// round 11
// baseline (speedup 1.0000x reference)
#include <cuda_runtime.h>
#include <math_constants.h>

// RoIPool: feature_map [B=2, H=50, W=50, C=256] f32, rpn_pred [B=2, N=128, 4] f32
// out [B, N, 7, 7, C] f32.
//   x1=(int)(W*p0); y1=(int)(H*p1); x2=(int)(W*p2); y2=(int)(H*p3)
//   sw=(x2-x1)/7; sh=(y2-y1)/7   (in [1,4] by input construction)
//   out[b,n,i,j,c] = max_{r<sh,t<sw} fm[b, y1+i*sh+r, x1+j*sw+t, c]
//
// R11: two-kernel range-max scheme to cut L2-served gather traffic 2.4x.
//  K1: pm22[b][y][x][c] = max over pixels {y,y+1}x{x,x+1} (clamped). 5 MB table.
//  K2: window max via exact 2-block decomposition per dim:
//      s=2 -> positions {0}; s=3 -> {0,1}; s=4 -> {0,2}  (pm22 reads)
//      s=1 -> direct fm reads for that dim.
//    Coverage is exact (union of 2-blocks == window, never exceeds it).
//  Avg reads/bin: 5.9 -> 2.54. Thread layout = R10 (16 ch/thread, warp=2 bins).

#define POOL 7
#define NROIS 128
#define BB 2
#define HH 50
#define WW 50
#define CC 256
#define C4 (CC / 4)   // 64 float4 per pixel
#define NBINS (POOL * POOL)       // 49
#define THREADS 160
#define ROWF4 (WW * C4)           // 3200 float4 per (b,y) row

__device__ float4 g_pm22[BB * HH * WW * C4];   // 5.12 MB scratch table

__device__ __forceinline__ void fmax4(float4& m, const float4 v) {
    m.x = fmaxf(m.x, v.x);
    m.y = fmaxf(m.y, v.y);
    m.z = fmaxf(m.z, v.z);
    m.w = fmaxf(m.w, v.w);
}

// ---------------- Kernel 1: 2x2 block max table ----------------
__global__ __launch_bounds__(THREADS) void pm22_kernel(
    const float4* __restrict__ fm)
{
    const int chunk = blockIdx.x;              // 0..3 quarter of a row
    const int y     = blockIdx.y;              // 0..49
    const int b     = blockIdx.z;              // 0..1
    const int yp    = min(y + 1, HH - 1);

    const float4* row0 = fm + (b * HH + y ) * ROWF4;
    const float4* row1 = fm + (b * HH + yp) * ROWF4;
    float4*       orow = g_pm22 + (b * HH + y) * ROWF4;

    #pragma unroll
    for (int k = 0; k < 5; ++k) {
        const int e = chunk * 800 + k * THREADS + threadIdx.x;  // 0..3199
        const int x  = e >> 6;
        const int c  = e & 63;
        const int xp = min(x + 1, WW - 1);
        float4 a = __ldg(row0 + x  * C4 + c);
        fmax4(a,  __ldg(row0 + xp * C4 + c));
        fmax4(a,  __ldg(row1 + x  * C4 + c));
        fmax4(a,  __ldg(row1 + xp * C4 + c));
        orow[e] = a;
    }
}

// ---------------- Kernel 2: pooled max from pm22 / fm ----------------

// One "cell" read = 4 float4 at stride 16 (16 channels/thread interleave).
__device__ __forceinline__ void cell16(const float4* __restrict__ p,
                                       float4 acc[4]) {
    float4 v0 = __ldg(p);
    float4 v1 = __ldg(p + 16);
    float4 v2 = __ldg(p + 32);
    float4 v3 = __ldg(p + 48);
    fmax4(acc[0], v0);
    fmax4(acc[1], v1);
    fmax4(acc[2], v2);
    fmax4(acc[3], v3);
}

template<int SH, int SW>
__device__ __forceinline__ void window_pm(const float4* __restrict__ fmbase,
                                          const float4* __restrict__ pmbase,
                                          float4 acc[4]) {
    if constexpr (SH >= 2 && SW >= 2) {
        // 2-block corner decomposition: exact window coverage via pm22.
        constexpr int NR = (SH == 2) ? 1 : 2;
        constexpr int NC = (SW == 2) ? 1 : 2;
        constexpr int DR = (SH == 4) ? 2 : 1;
        constexpr int DC = (SW == 4) ? 2 : 1;
        #pragma unroll
        for (int r = 0; r < NR; ++r)
            #pragma unroll
            for (int c = 0; c < NC; ++c)
                cell16(pmbase + (r * DR * WW + c * DC) * C4, acc);
    } else if constexpr (SH == 1 && SW == 1) {
        cell16(fmbase, acc);
    } else if constexpr (SH == 1) {
        #pragma unroll
        for (int t = 0; t < SW; ++t)
            cell16(fmbase + t * C4, acc);
    } else {  // SW == 1
        #pragma unroll
        for (int r = 0; r < SH; ++r)
            cell16(fmbase + r * WW * C4, acc);
    }
}

__global__ __launch_bounds__(THREADS, 9) void roi_pool_kernel(
    const float4* __restrict__ fm,     // [B*H*W*C4] float4
    const float4* __restrict__ rois,   // [B*N] float4 (x1,y1,x2,y2)
    float4*       __restrict__ out)    // [B*N*49*C4] float4
{
    const int warp = threadIdx.x >> 5;          // 0..4
    const int lane = threadIdx.x & 31;
    const int half = lane >> 4;                 // which bin of the warp
    const int t16  = lane & 15;                 // channel group 0..15

    const int n = blockIdx.y;
    const int b = blockIdx.z;

    const int bin  = blockIdx.x * 10 + warp * 2 + half;  // 0..49
    const bool valid = (bin < NBINS);
    const int binc = valid ? bin : (NBINS - 1);          // phantom -> alias 48

    const float4 rp = __ldg(rois + b * NROIS + n);
    const int x1 = (int)(WW * rp.x);
    const int y1 = (int)(HH * rp.y);
    const int sw = ((int)(WW * rp.z) - x1) / POOL;   // in [1,4]
    const int sh = ((int)(HH * rp.w) - y1) / POOL;   // in [1,4]

    const int i = binc / POOL;
    const int j = binc - i * POOL;

    const int cellOff = ((b * HH + (y1 + i * sh)) * WW + (x1 + j * sw)) * C4 + t16;
    const float4* fmbase = fm + cellOff;
    const float4* pmbase = g_pm22 + cellOff;

    const float NEG = -CUDART_INF_F;
    float4 acc[4];
    #pragma unroll
    for (int k = 0; k < 4; ++k) acc[k] = make_float4(NEG, NEG, NEG, NEG);

    // CTA-uniform 16-way dispatch on (sh,sw).
    const int code = (sh - 1) * 4 + (sw - 1);
    switch (code) {
        case  0: window_pm<1,1>(fmbase, pmbase, acc); break;
        case  1: window_pm<1,2>(fmbase, pmbase, acc); break;
        case  2: window_pm<1,3>(fmbase, pmbase, acc); break;
        case  3: window_pm<1,4>(fmbase, pmbase, acc); break;
        case  4: window_pm<2,1>(fmbase, pmbase, acc); break;
        case  5: window_pm<2,2>(fmbase, pmbase, acc); break;
        case  6: window_pm<2,3>(fmbase, pmbase, acc); break;
        case  7: window_pm<2,4>(fmbase, pmbase, acc); break;
        case  8: window_pm<3,1>(fmbase, pmbase, acc); break;
        case  9: window_pm<3,2>(fmbase, pmbase, acc); break;
        case 10: window_pm<3,3>(fmbase, pmbase, acc); break;
        case 11: window_pm<3,4>(fmbase, pmbase, acc); break;
        case 12: window_pm<4,1>(fmbase, pmbase, acc); break;
        case 13: window_pm<4,2>(fmbase, pmbase, acc); break;
        case 14: window_pm<4,3>(fmbase, pmbase, acc); break;
        default: window_pm<4,4>(fmbase, pmbase, acc); break;
    }

    if (valid) {
        float4* obase = out + ((b * NROIS + n) * NBINS + bin) * C4 + t16;
        obase[0]  = acc[0];
        obase[16] = acc[1];
        obase[32] = acc[2];
        obase[48] = acc[3];
    }
}

extern "C" void kernel_launch(void* const* d_in, const int* in_sizes, int n_in,
                              void* d_out, int out_size) {
    const float4* fm   = (const float4*)d_in[0];  // feature_map
    const float4* rois = (const float4*)d_in[1];  // rpn_pred as float4
    float4*       out  = (float4*)d_out;

    dim3 g1(4, HH, BB);                           // 400 CTAs
    pm22_kernel<<<g1, THREADS>>>(fm);

    dim3 g2(5, NROIS, BB);                        // 1280 CTAs
    roi_pool_kernel<<<g2, THREADS>>>(fm, rois, out);
}

// round 12
// speedup vs baseline: 1.0985x; 1.0985x over previous
#include <cuda_runtime.h>
#include <math_constants.h>

// RoIPool: feature_map [B=2, H=50, W=50, C=256] f32, rpn_pred [B=2, N=128, 4] f32
// out [B, N, 7, 7, C] f32.
//   x1=(int)(W*p0); y1=(int)(H*p1); x2=(int)(W*p2); y2=(int)(H*p3)
//   sw=(x2-x1)/7; sh=(y2-y1)/7   (in [1,4] by input construction)
//   out[b,n,i,j,c] = max_{r<sh,t<sw} fm[b, y1+i*sh+r, x1+j*sw+t, c]
// Bounds: x1+7*sw-1 <= x2-1 <= 49 (same for y) -> reference clip is dead code.
//
// R12: ILP-first. warp = ONE bin, thread = 8 channels (2 float4 accumulators,
// lane covers f4 indices {lane, lane+32}). CTA = 224 threads = 7 bins; grid
// (7,128,2) covers all 49 bins exactly (no phantoms). Window cells processed
// in chunks of 4: ALL 8 float4 loads of a chunk are issued before any fmax
// (explicit register staging, launch_bounds(224,4) -> ~71 regs so ptxas does
// not re-serialize). Serialized L2 exposures per thread: ~6 -> ceil(cells/4).

#define POOL 7
#define NROIS 128
#define BB 2
#define HH 50
#define WW 50
#define CC 256
#define C4 (CC / 4)   // 64 float4 per pixel
#define NBINS (POOL * POOL)       // 49
#define THREADS 224               // 7 warps = 7 bins

__device__ __forceinline__ void fmax4(float4& m, const float4 v) {
    m.x = fmaxf(m.x, v.x);
    m.y = fmaxf(m.y, v.y);
    m.z = fmaxf(m.z, v.z);
    m.w = fmaxf(m.w, v.w);
}

// Exact SHxSW window, 2 float4 per cell per thread, chunks of 4 cells:
// loads of a chunk fully issued before any consumption.
template<int SH, int SW>
__device__ __forceinline__ void window8(const float4* __restrict__ base,
                                        float4& acc0, float4& acc1) {
    constexpr int NCELL = SH * SW;
    constexpr int NCHUNK = (NCELL + 3) / 4;
    #pragma unroll
    for (int g = 0; g < NCHUNK; ++g) {
        float4 buf0[4], buf1[4];
        // Issue phase: up to 8 independent LDG.128, compile-time offsets.
        #pragma unroll
        for (int u = 0; u < 4; ++u) {
            constexpr_helper:;
            const int k = g * 4 + u;
            if (k < NCELL) {
                const int r = k / SW;
                const int t = k - r * SW;
                const float4* cp = base + (r * WW + t) * C4;
                buf0[u] = __ldg(cp);
                buf1[u] = __ldg(cp + 32);
            }
        }
        // Consume phase.
        #pragma unroll
        for (int u = 0; u < 4; ++u) {
            const int k = g * 4 + u;
            if (k < NCELL) {
                fmax4(acc0, buf0[u]);
                fmax4(acc1, buf1[u]);
            }
        }
    }
}

__global__ __launch_bounds__(THREADS, 4) void roi_pool_kernel(
    const float4* __restrict__ fm,     // [B*H*W*C4] float4
    const float4* __restrict__ rois,   // [B*N] float4 (x1,y1,x2,y2)
    float4*       __restrict__ out)    // [B*N*49*C4] float4
{
    const int warp = threadIdx.x >> 5;          // 0..6
    const int lane = threadIdx.x & 31;          // f4 index base

    const int bin = blockIdx.x * POOL + warp;   // 0..48 exact
    const int n   = blockIdx.y;
    const int b   = blockIdx.z;

    const float4 rp = __ldg(rois + b * NROIS + n);
    const int x1 = (int)(WW * rp.x);
    const int y1 = (int)(HH * rp.y);
    const int sw = ((int)(WW * rp.z) - x1) / POOL;   // in [1,4]
    const int sh = ((int)(HH * rp.w) - y1) / POOL;   // in [1,4]

    const int i = bin / POOL;
    const int j = bin - i * POOL;

    // Thread covers float4 indices {lane, lane+32} of each pixel.
    const float4* base =
        fm + ((b * HH + (y1 + i * sh)) * WW + (x1 + j * sw)) * C4 + lane;

    const float NEG = -CUDART_INF_F;
    float4 acc0 = make_float4(NEG, NEG, NEG, NEG);
    float4 acc1 = make_float4(NEG, NEG, NEG, NEG);

    // CTA-uniform 16-way dispatch on (sh,sw).
    const int code = (sh - 1) * 4 + (sw - 1);
    switch (code) {
        case  0: window8<1,1>(base, acc0, acc1); break;
        case  1: window8<1,2>(base, acc0, acc1); break;
        case  2: window8<1,3>(base, acc0, acc1); break;
        case  3: window8<1,4>(base, acc0, acc1); break;
        case  4: window8<2,1>(base, acc0, acc1); break;
        case  5: window8<2,2>(base, acc0, acc1); break;
        case  6: window8<2,3>(base, acc0, acc1); break;
        case  7: window8<2,4>(base, acc0, acc1); break;
        case  8: window8<3,1>(base, acc0, acc1); break;
        case  9: window8<3,2>(base, acc0, acc1); break;
        case 10: window8<3,3>(base, acc0, acc1); break;
        case 11: window8<3,4>(base, acc0, acc1); break;
        case 12: window8<4,1>(base, acc0, acc1); break;
        case 13: window8<4,2>(base, acc0, acc1); break;
        case 14: window8<4,3>(base, acc0, acc1); break;
        default: window8<4,4>(base, acc0, acc1); break;
    }

    float4* obase = out + ((b * NROIS + n) * NBINS + bin) * C4 + lane;
    obase[0]  = acc0;
    obase[32] = acc1;
}

extern "C" void kernel_launch(void* const* d_in, const int* in_sizes, int n_in,
                              void* d_out, int out_size) {
    const float4* fm   = (const float4*)d_in[0];  // feature_map
    const float4* rois = (const float4*)d_in[1];  // rpn_pred as float4
    float4*       out  = (float4*)d_out;

    dim3 grid(POOL, NROIS, BB);                   // 7 x 128 x 2 = 1792 CTAs
    roi_pool_kernel<<<grid, THREADS>>>(fm, rois, out);
}